// round 1
// baseline (speedup 1.0000x reference)
#include <cuda_runtime.h>
#include <cuda_bf16.h>
#include <math.h>

// Detector: per-submap (1024 pts) -> top-512 by xy-dist -> FPS 32 -> gather MLP scores.
// One CTA per submap. MLP deferred to only the 32 selected points (scores do not
// affect index selection), eliminating 97% of FMA work and the 256MB x-matrix read.

#define NPTS   1024
#define KPOS   512
#define KSEL   32
#define THREADS 512

// shared weight layout offsets (floats)
#define W1_OFF 0      // 32*16 = 512
#define B1_OFF 512    // 16
#define W2_OFF 528    // 16*8 = 128
#define B2_OFF 656    // 8
#define W3_OFF 664    // 8
#define B3_OFF 672    // 1
#define WTOT   673

__global__ __launch_bounds__(THREADS) void detector_kernel(
    const float* __restrict__ x,    // [B*1024, 32]
    const float* __restrict__ pos,  // [B*1024, 3]
    const float* __restrict__ W1, const float* __restrict__ b1,
    const float* __restrict__ W2, const float* __restrict__ b2,
    const float* __restrict__ W3, const float* __restrict__ b3,
    float* __restrict__ out_w,      // [B, 32]
    float* __restrict__ out_i)      // [B, 32] (indices as float)
{
    __shared__ float skey[NPTS];
    __shared__ int   sval[NPTS];
    __shared__ float selp[KPOS * 3];
    __shared__ float wsh[WTOT];
    __shared__ float red_v[16];
    __shared__ int   red_i[16];
    __shared__ int   chosen[KSEL];
    __shared__ int   cidx;

    const int b = blockIdx.x;
    const int t = threadIdx.x;
    const size_t base = (size_t)b * NPTS;

    // ---- load MLP weights to shared ----
    for (int i = t; i < WTOT; i += THREADS) {
        float v;
        if (i < B1_OFF)       v = W1[i];
        else if (i < W2_OFF)  v = b1[i - B1_OFF];
        else if (i < B2_OFF)  v = W2[i - W2_OFF];
        else if (i < W3_OFF)  v = b2[i - B2_OFF];
        else if (i < B3_OFF)  v = W3[i - W3_OFF];
        else                  v = b3[0];
        wsh[i] = v;
    }

    // ---- xy distance keys (match jnp.linalg.norm: sqrt(px*px+py*py), no FMA, IEEE sqrt) ----
    for (int i = t; i < NPTS; i += THREADS) {
        float px = pos[(base + i) * 3 + 0];
        float py = pos[(base + i) * 3 + 1];
        float s2 = __fadd_rn(__fmul_rn(px, px), __fmul_rn(py, py));
        skey[i] = __fsqrt_rn(s2);
        sval[i] = i;
    }
    __syncthreads();

    // ---- bitonic sort ascending by (dist, idx) -- matches lax.top_k(-dist) tie rules ----
    for (int k = 2; k <= NPTS; k <<= 1) {
        for (int j = k >> 1; j > 0; j >>= 1) {
            #pragma unroll
            for (int s = 0; s < NPTS / THREADS; s++) {
                int tid = t + s * THREADS;
                int ixj = tid ^ j;
                if (ixj > tid) {
                    float ka = skey[tid], kb = skey[ixj];
                    int   va = sval[tid], vb = sval[ixj];
                    bool aLb = (ka < kb) || (ka == kb && va < vb);
                    bool up  = ((tid & k) == 0);
                    if (up ? !aLb : aLb) {
                        skey[tid] = kb; skey[ixj] = ka;
                        sval[tid] = vb; sval[ixj] = va;
                    }
                }
            }
            __syncthreads();
        }
    }

    // ---- FPS over the 512 closest (thread t owns selected point t) ----
    int   myorig = sval[t];                       // t < 512 always (THREADS==KPOS)
    float mpx = pos[(base + myorig) * 3 + 0];
    float mpy = pos[(base + myorig) * 3 + 1];
    float mpz = pos[(base + myorig) * 3 + 2];
    selp[t * 3 + 0] = mpx;
    selp[t * 3 + 1] = mpy;
    selp[t * 3 + 2] = mpz;
    if (t == 0) chosen[0] = 0;
    __syncthreads();

    // initial min_d = ||p - p0||^2, sum order (dx2+dy2)+dz2, no FMA contraction
    float qx = selp[0], qy = selp[1], qz = selp[2];
    float dx = __fsub_rn(mpx, qx), dy = __fsub_rn(mpy, qy), dz = __fsub_rn(mpz, qz);
    float mind = __fadd_rn(__fadd_rn(__fmul_rn(dx, dx), __fmul_rn(dy, dy)), __fmul_rn(dz, dz));

    const unsigned FULL = 0xffffffffu;
    const int lane = t & 31, warp = t >> 5;

    for (int it = 1; it < KSEL; ++it) {
        // argmax(min_d) with first-index tie-break (matches jnp.argmax)
        float v = mind; int idx = t;
        #pragma unroll
        for (int off = 16; off > 0; off >>= 1) {
            float v2 = __shfl_down_sync(FULL, v, off);
            int   i2 = __shfl_down_sync(FULL, idx, off);
            if (v2 > v || (v2 == v && i2 < idx)) { v = v2; idx = i2; }
        }
        if (lane == 0) { red_v[warp] = v; red_i[warp] = idx; }
        __syncthreads();
        if (warp == 0) {
            float vv = (lane < 16) ? red_v[lane] : -1e30f;
            int   ii = (lane < 16) ? red_i[lane] : 0x7fffffff;
            #pragma unroll
            for (int off = 16; off > 0; off >>= 1) {
                float v2 = __shfl_down_sync(FULL, vv, off);
                int   i2 = __shfl_down_sync(FULL, ii, off);
                if (v2 > vv || (v2 == vv && i2 < ii)) { vv = v2; ii = i2; }
            }
            if (lane == 0) { cidx = ii; chosen[it] = ii; }
        }
        __syncthreads();

        int ci = cidx;
        float cx = selp[ci * 3 + 0], cy = selp[ci * 3 + 1], cz = selp[ci * 3 + 2];
        float ex = __fsub_rn(mpx, cx), ey = __fsub_rn(mpy, cy), ez = __fsub_rn(mpz, cz);
        float d2 = __fadd_rn(__fadd_rn(__fmul_rn(ex, ex), __fmul_rn(ey, ey)), __fmul_rn(ez, ez));
        mind = fminf(mind, d2);
        // red_v/red_i writes of next iter can't race cidx reads (2 barriers per iter)
    }
    __syncthreads();

    // ---- MLP only for the 32 selected points, then gather + write ----
    if (t < KSEL) {
        int sel  = chosen[t];
        int orig = sval[sel];
        const float* xr = x + (base + orig) * 32;
        float xv[32];
        #pragma unroll
        for (int i = 0; i < 32; i++) xv[i] = xr[i];

        float h1[16];
        #pragma unroll
        for (int o = 0; o < 16; o++) {
            float a = wsh[B1_OFF + o];
            #pragma unroll
            for (int i = 0; i < 32; i++) a = fmaf(xv[i], wsh[W1_OFF + i * 16 + o], a);
            h1[o] = fmaxf(a, 0.0f);
        }
        float h2[8];
        #pragma unroll
        for (int o = 0; o < 8; o++) {
            float a = wsh[B2_OFF + o];
            #pragma unroll
            for (int i = 0; i < 16; i++) a = fmaf(h1[i], wsh[W2_OFF + i * 8 + o], a);
            h2[o] = fmaxf(a, 0.0f);
        }
        float s = wsh[B3_OFF];
        #pragma unroll
        for (int i = 0; i < 8; i++) s = fmaf(h2[i], wsh[W3_OFF + i], s);
        // softplus = max(s,0) + log1p(exp(-|s|))  (matches jax.nn.softplus)
        float sp = fmaxf(s, 0.0f) + log1pf(expf(-fabsf(s)));

        out_w[(size_t)b * KSEL + t] = sp;
        out_i[(size_t)b * KSEL + t] = (float)orig;
    }
}

extern "C" void kernel_launch(void* const* d_in, const int* in_sizes, int n_in,
                              void* d_out, int out_size) {
    const float* x   = (const float*)d_in[0];
    const float* pos = (const float*)d_in[1];
    // d_in[2] = batch (int32) -- implied by layout, unused
    const float* W1  = (const float*)d_in[3];
    const float* b1  = (const float*)d_in[4];
    const float* W2  = (const float*)d_in[5];
    const float* b2  = (const float*)d_in[6];
    const float* W3  = (const float*)d_in[7];
    const float* b3  = (const float*)d_in[8];

    int n_points = in_sizes[0] / 32;      // B * 1024
    int B = n_points / NPTS;

    float* out_w = (float*)d_out;
    float* out_i = out_w + (size_t)B * KSEL;   // second tuple element (indices as float)

    detector_kernel<<<B, THREADS>>>(x, pos, W1, b1, W2, b2, W3, b3, out_w, out_i);
}

// round 2
// speedup vs baseline: 1.4713x; 1.4713x over previous
#include <cuda_runtime.h>
#include <cuda_bf16.h>
#include <math.h>

// Detector: per-submap (1024 pts) -> top-512 by xy-dist -> FPS 32 -> gather MLP scores.
// Kernel 1: packed-u64 bitonic sort (register/shfl for j<=32 stages) + FPS.
// Kernel 2: tiny MLP only on the 2048*32 selected points.

#define NPTS    1024
#define KPOS    512
#define KSEL    32
#define THREADS 512

typedef unsigned long long u64;
typedef unsigned int u32;

__device__ __forceinline__ u64 shfl_xor_u64(u64 v, int m) {
    u32 lo = __shfl_xor_sync(0xffffffffu, (u32)v, m);
    u32 hi = __shfl_xor_sync(0xffffffffu, (u32)(v >> 32), m);
    return ((u64)hi << 32) | lo;
}
__device__ __forceinline__ u64 umin64(u64 a, u64 b) { return a < b ? a : b; }
__device__ __forceinline__ u64 umax64(u64 a, u64 b) { return a > b ? a : b; }

// In-register stages of bitonic round K: j = 32 (if K>=64) then 16..1.
// Thread (warp w, lane l) owns elements i0 = w*64+l and i1 = i0+32.
template<int K>
__device__ __forceinline__ void reg_stages(u64& e0, u64& e1, int i0, int i1, int l) {
    if (K >= 64) {
        bool up = ((i0 & K) == 0);          // same bit for i0 and i1 (K >= 64)
        u64 lo = umin64(e0, e1), hi = umax64(e0, e1);
        e0 = up ? lo : hi;
        e1 = up ? hi : lo;
    }
    const bool up0 = ((i0 & K) == 0);
    const bool up1 = ((i1 & K) == 0);
    #pragma unroll
    for (int j = (K >= 32 ? 16 : (K >> 1)); j >= 1; j >>= 1) {
        bool lower = ((l & j) == 0);        // this element is the lower of its pair
        u64 p0 = shfl_xor_u64(e0, j);
        e0 = ((lower == up0) ? umin64(e0, p0) : umax64(e0, p0));
        u64 p1 = shfl_xor_u64(e1, j);
        e1 = ((lower == up1) ? umin64(e1, p1) : umax64(e1, p1));
    }
}

__device__ __forceinline__ void shared_pass(u64* skv, int t, int j, int k) {
    int i = ((t & ~(j - 1)) << 1) | (t & (j - 1));   // pair (i, i+j)
    int p = i + j;
    bool up = ((i & k) == 0);
    u64 a = skv[i], b = skv[p];
    u64 lo = umin64(a, b), hi = umax64(a, b);
    skv[i] = up ? lo : hi;
    skv[p] = up ? hi : lo;
}

__global__ __launch_bounds__(THREADS, 4) void sort_fps_kernel(
    const float* __restrict__ pos,   // [B*1024, 3]
    float* __restrict__ out_i)       // [B, 32] indices (as float)
{
    __shared__ u64   skv[NPTS];        // 8KB packed (distbits<<32)|idx
    __shared__ float selp[KPOS * 3];   // 6KB selected xyz
    __shared__ u64   slots[KSEL];      // per-iteration argmax slots

    const int b = blockIdx.x;
    const int t = threadIdx.x;
    const int l = t & 31;
    const int i0 = ((t >> 5) << 6) + l;   // warp*64 + lane
    const int i1 = i0 + 32;
    const size_t base = (size_t)b * NPTS;

    // ---- keys: xy norm (exact rn ops, no FMA), packed with index ----
    u64 e0, e1;
    {
        float px = pos[(base + i0) * 3 + 0];
        float py = pos[(base + i0) * 3 + 1];
        float d  = __fsqrt_rn(__fadd_rn(__fmul_rn(px, px), __fmul_rn(py, py)));
        e0 = ((u64)__float_as_uint(d) << 32) | (u32)i0;
        px = pos[(base + i1) * 3 + 0];
        py = pos[(base + i1) * 3 + 1];
        d  = __fsqrt_rn(__fadd_rn(__fmul_rn(px, px), __fmul_rn(py, py)));
        e1 = ((u64)__float_as_uint(d) << 32) | (u32)i1;
    }

    // ---- rounds k=2..64 fully in registers (no barriers) ----
    reg_stages<2>(e0, e1, i0, i1, l);
    reg_stages<4>(e0, e1, i0, i1, l);
    reg_stages<8>(e0, e1, i0, i1, l);
    reg_stages<16>(e0, e1, i0, i1, l);
    reg_stages<32>(e0, e1, i0, i1, l);
    reg_stages<64>(e0, e1, i0, i1, l);

    // ---- rounds k=128..1024: shared passes for j>=64, then register tail ----
    #pragma unroll
    for (int k = 128; k <= 1024; k <<= 1) {
        skv[i0] = e0; skv[i1] = e1;
        __syncthreads();
        for (int j = k >> 1; j >= 64; j >>= 1) {
            shared_pass(skv, t, j, k);
            __syncthreads();
        }
        e0 = skv[i0]; e1 = skv[i1];
        switch (k) {
            case 128:  reg_stages<128>(e0, e1, i0, i1, l); break;
            case 256:  reg_stages<256>(e0, e1, i0, i1, l); break;
            case 512:  reg_stages<512>(e0, e1, i0, i1, l); break;
            default:   reg_stages<1024>(e0, e1, i0, i1, l); break;
        }
    }

    // publish sorted ranks
    skv[i0] = e0; skv[i1] = e1;
    if (t < KSEL) slots[t] = 0ull;
    __syncthreads();

    // ---- FPS: thread t owns rank t (t < 512) ----
    const int myorig = (int)(u32)skv[t];
    const float mpx = pos[(base + myorig) * 3 + 0];
    const float mpy = pos[(base + myorig) * 3 + 1];
    const float mpz = pos[(base + myorig) * 3 + 2];
    selp[t * 3 + 0] = mpx;
    selp[t * 3 + 1] = mpy;
    selp[t * 3 + 2] = mpz;
    if (t == 0) out_i[(size_t)b * KSEL + 0] = (float)myorig;
    __syncthreads();

    // initial min_d vs rank-0 point: (dx2+dy2)+dz2, exact rn ops
    float qx = selp[0], qy = selp[1], qz = selp[2];
    float dx = __fsub_rn(mpx, qx), dy = __fsub_rn(mpy, qy), dz = __fsub_rn(mpz, qz);
    float mind = __fadd_rn(__fadd_rn(__fmul_rn(dx, dx), __fmul_rn(dy, dy)), __fmul_rn(dz, dz));

    for (int it = 1; it < KSEL; ++it) {
        // packed argmax: (mind_bits << 32) | (511 - rank)  -> max = max val, tie = min rank
        u64 v = ((u64)__float_as_uint(mind) << 32) | (u32)(511 - t);
        #pragma unroll
        for (int o = 16; o >= 1; o >>= 1)
            v = umax64(v, shfl_xor_u64(v, o));
        if (l == 0) atomicMax(&slots[it], v);
        __syncthreads();
        u64 w = slots[it];
        int sel = 511 - (int)(u32)w;
        if (t == sel) out_i[(size_t)b * KSEL + it] = (float)myorig;

        float cx = selp[sel * 3 + 0], cy = selp[sel * 3 + 1], cz = selp[sel * 3 + 2];
        float ex = __fsub_rn(mpx, cx), ey = __fsub_rn(mpy, cy), ez = __fsub_rn(mpz, cz);
        float d2 = __fadd_rn(__fadd_rn(__fmul_rn(ex, ex), __fmul_rn(ey, ey)), __fmul_rn(ez, ez));
        mind = fminf(mind, d2);
    }
}

// ---- kernel 2: MLP + softplus only for the selected points ----
__global__ __launch_bounds__(256) void mlp_kernel(
    const float* __restrict__ x,      // [B*1024, 32]
    const float* __restrict__ W1, const float* __restrict__ b1,
    const float* __restrict__ W2, const float* __restrict__ b2,
    const float* __restrict__ W3, const float* __restrict__ b3,
    const float* __restrict__ out_i,  // [B*32] indices as float (written by kernel 1)
    float* __restrict__ out_w,        // [B*32]
    int total)
{
    int t = blockIdx.x * blockDim.x + threadIdx.x;
    if (t >= total) return;
    int submap = t >> 5;             // KSEL == 32
    int orig = (int)out_i[t];
    const float* xr = x + ((size_t)submap * NPTS + orig) * 32;

    float xv[32];
    #pragma unroll
    for (int i = 0; i < 32; i++) xv[i] = xr[i];

    float h1[16];
    #pragma unroll
    for (int o = 0; o < 16; o++) {
        float a = __ldg(&b1[o]);
        #pragma unroll
        for (int i = 0; i < 32; i++) a = fmaf(xv[i], __ldg(&W1[i * 16 + o]), a);
        h1[o] = fmaxf(a, 0.0f);
    }
    float h2[8];
    #pragma unroll
    for (int o = 0; o < 8; o++) {
        float a = __ldg(&b2[o]);
        #pragma unroll
        for (int i = 0; i < 16; i++) a = fmaf(h1[i], __ldg(&W2[i * 8 + o]), a);
        h2[o] = fmaxf(a, 0.0f);
    }
    float s = __ldg(&b3[0]);
    #pragma unroll
    for (int i = 0; i < 8; i++) s = fmaf(h2[i], __ldg(&W3[i]), s);
    float sp = fmaxf(s, 0.0f) + log1pf(expf(-fabsf(s)));
    out_w[t] = sp;
}

extern "C" void kernel_launch(void* const* d_in, const int* in_sizes, int n_in,
                              void* d_out, int out_size) {
    const float* x   = (const float*)d_in[0];
    const float* pos = (const float*)d_in[1];
    const float* W1  = (const float*)d_in[3];
    const float* b1  = (const float*)d_in[4];
    const float* W2  = (const float*)d_in[5];
    const float* b2  = (const float*)d_in[6];
    const float* W3  = (const float*)d_in[7];
    const float* b3  = (const float*)d_in[8];

    int n_points = in_sizes[0] / 32;      // B * 1024
    int B = n_points / NPTS;

    float* out_w = (float*)d_out;
    float* out_i = out_w + (size_t)B * KSEL;

    sort_fps_kernel<<<B, THREADS>>>(pos, out_i);

    int total = B * KSEL;
    mlp_kernel<<<(total + 255) / 256, 256>>>(x, W1, b1, W2, b2, W3, b3, out_i, out_w, total);
}

// round 3
// speedup vs baseline: 2.5745x; 1.7498x over previous
#include <cuda_runtime.h>
#include <cuda_bf16.h>
#include <math.h>

// Detector: per-submap (1024 pts) -> top-512 by xy-dist (rank-ordered) -> FPS 32 -> MLP gather.
// K1: bitonic sort, 256 thr x 4 elem (register exchanges for j<=64), writes ranked float4 scratch.
// K2: one warp per submap: register-resident FPS (16 pts/lane) + fused per-point MLP.

#define NPTS 1024
#define KPOS 512
#define KSEL 32
#define T1   256
#define BMAX 2048

typedef unsigned long long u64;
typedef unsigned int u32;

__device__ float4 g_selp[(size_t)BMAX * KPOS];   // 16.8 MB static scratch

__device__ __forceinline__ u64 shfl_xor_u64(u64 v, int m) {
    u32 lo = __shfl_xor_sync(0xffffffffu, (u32)v, m);
    u32 hi = __shfl_xor_sync(0xffffffffu, (u32)(v >> 32), m);
    return ((u64)hi << 32) | lo;
}
__device__ __forceinline__ u64 umin64(u64 a, u64 b) { return a < b ? a : b; }
__device__ __forceinline__ u64 umax64(u64 a, u64 b) { return a > b ? a : b; }

// cross-lane stages j = JMAX..1 of round k (element i_m = w*128 + m*32 + l)
template<int JMAX>
__device__ __forceinline__ void shfl_steps(u64* e, int l, int w, unsigned k) {
    #pragma unroll
    for (int j = JMAX; j >= 1; j >>= 1) {
        #pragma unroll
        for (int m = 0; m < 4; m++) {
            int i = (w << 7) + (m << 5) + l;
            bool up = ((i & k) == 0);
            bool lower = ((l & j) == 0);
            u64 p = shfl_xor_u64(e[m], j);
            e[m] = (lower == up) ? umin64(e[m], p) : umax64(e[m], p);
        }
    }
}

// intra-thread stage: j = 32<<mbit, pairs (m, m ^ (1<<mbit))
__device__ __forceinline__ void intra_step(u64* e, int l, int w, unsigned k, int mbit) {
    #pragma unroll
    for (int m = 0; m < 4; m++) {
        int mp = m ^ (1 << mbit);
        if (mp > m) {
            int i = (w << 7) + (m << 5) + l;
            bool up = ((i & k) == 0);
            u64 lo = umin64(e[m], e[mp]), hi = umax64(e[m], e[mp]);
            e[m] = up ? lo : hi;
            e[mp] = up ? hi : lo;
        }
    }
}

// shared stage for j >= 128 (two pairs per thread)
__device__ __forceinline__ void shared_pass2(u64* skv, int t, int j, unsigned k) {
    #pragma unroll
    for (int s = 0; s < 2; s++) {
        int tt = t + s * T1;
        int i = ((tt & ~(j - 1)) << 1) | (tt & (j - 1));
        int p = i + j;
        bool up = ((i & k) == 0);
        u64 a = skv[i], b = skv[p];
        u64 lo = umin64(a, b), hi = umax64(a, b);
        skv[i] = up ? lo : hi;
        skv[p] = up ? hi : lo;
    }
}

__device__ __forceinline__ void store_regs(u64* skv, const u64* e, int l, int w) {
    #pragma unroll
    for (int m = 0; m < 4; m++) skv[(w << 7) + (m << 5) + l] = e[m];
}
__device__ __forceinline__ void load_regs(u64* skv, u64* e, int l, int w) {
    #pragma unroll
    for (int m = 0; m < 4; m++) e[m] = skv[(w << 7) + (m << 5) + l];
}

__global__ __launch_bounds__(T1, 6) void sort_kernel(const float* __restrict__ pos)
{
    __shared__ u64 skv[NPTS];
    const int b = blockIdx.x;
    const int t = threadIdx.x;
    const int l = t & 31, w = t >> 5;
    const size_t base = (size_t)b * NPTS;

    u64 e[4];
    #pragma unroll
    for (int m = 0; m < 4; m++) {
        int i = (w << 7) + (m << 5) + l;
        float px = pos[(base + i) * 3 + 0];
        float py = pos[(base + i) * 3 + 1];
        float d = __fsqrt_rn(__fadd_rn(__fmul_rn(px, px), __fmul_rn(py, py)));
        e[m] = ((u64)__float_as_uint(d) << 32) | (u32)i;
    }

    // rounds k=2..128: registers only
    shfl_steps<1>(e, l, w, 2u);
    shfl_steps<2>(e, l, w, 4u);
    shfl_steps<4>(e, l, w, 8u);
    shfl_steps<8>(e, l, w, 16u);
    shfl_steps<16>(e, l, w, 32u);
    intra_step(e, l, w, 64u, 0);  shfl_steps<16>(e, l, w, 64u);
    intra_step(e, l, w, 128u, 1); intra_step(e, l, w, 128u, 0); shfl_steps<16>(e, l, w, 128u);

    // k=256
    store_regs(skv, e, l, w); __syncthreads();
    shared_pass2(skv, t, 128, 256u); __syncthreads();
    load_regs(skv, e, l, w);
    intra_step(e, l, w, 256u, 1); intra_step(e, l, w, 256u, 0); shfl_steps<16>(e, l, w, 256u);

    // k=512
    store_regs(skv, e, l, w); __syncthreads();
    shared_pass2(skv, t, 256, 512u); __syncthreads();
    shared_pass2(skv, t, 128, 512u); __syncthreads();
    load_regs(skv, e, l, w);
    intra_step(e, l, w, 512u, 1); intra_step(e, l, w, 512u, 0); shfl_steps<16>(e, l, w, 512u);

    // k=1024
    store_regs(skv, e, l, w); __syncthreads();
    shared_pass2(skv, t, 512, 1024u); __syncthreads();
    shared_pass2(skv, t, 256, 1024u); __syncthreads();
    shared_pass2(skv, t, 128, 1024u); __syncthreads();
    load_regs(skv, e, l, w);
    intra_step(e, l, w, 1024u, 1); intra_step(e, l, w, 1024u, 0); shfl_steps<16>(e, l, w, 1024u);

    // ranks 0..511 live in warps 0..3; write (x,y,z,origidx) in rank order
    if (w < 4) {
        #pragma unroll
        for (int m = 0; m < 4; m++) {
            int rank = (w << 7) + (m << 5) + l;
            int orig = (int)(u32)e[m];
            const float* pp = pos + (base + orig) * 3;
            g_selp[(size_t)b * KPOS + rank] = make_float4(pp[0], pp[1], pp[2], (float)orig);
        }
    }
}

__global__ __launch_bounds__(32) void fps_mlp_kernel(
    const float* __restrict__ x,
    const float* __restrict__ W1, const float* __restrict__ b1,
    const float* __restrict__ W2, const float* __restrict__ b2,
    const float* __restrict__ W3, const float* __restrict__ b3,
    float* __restrict__ out_w, float* __restrict__ out_i)
{
    __shared__ float4 selp[KPOS];   // broadcast lookup of chosen point
    __shared__ int chosen[KSEL];

    const int b = blockIdx.x;
    const int l = threadIdx.x;

    float px[16], py[16], pz[16];
    #pragma unroll
    for (int m = 0; m < 16; m++) {
        float4 f = g_selp[(size_t)b * KPOS + (m << 5) + l];
        selp[(m << 5) + l] = f;
        px[m] = f.x; py[m] = f.y; pz[m] = f.z;
    }
    __syncwarp();

    float4 p0 = selp[0];
    if (l == 0) {
        out_i[(size_t)b * KSEL + 0] = p0.w;
        chosen[0] = (int)p0.w;
    }

    float mind[16];
    #pragma unroll
    for (int m = 0; m < 16; m++) {
        float dx = __fsub_rn(px[m], p0.x), dy = __fsub_rn(py[m], p0.y), dz = __fsub_rn(pz[m], p0.z);
        mind[m] = __fadd_rn(__fadd_rn(__fmul_rn(dx, dx), __fmul_rn(dy, dy)), __fmul_rn(dz, dz));
    }

    for (int it = 1; it < KSEL; ++it) {
        // argmax with min-rank tie-break: key = (mindbits << 32) | (511 - rank)
        u64 best = 0ull;
        #pragma unroll
        for (int m = 0; m < 16; m++) {
            u64 v = ((u64)__float_as_uint(mind[m]) << 32) | (u32)(511 - ((m << 5) + l));
            best = umax64(best, v);
        }
        #pragma unroll
        for (int o = 16; o >= 1; o >>= 1)
            best = umax64(best, shfl_xor_u64(best, o));
        int sel = 511 - (int)(u32)best;

        float4 c = selp[sel];        // same address across warp -> broadcast
        if (l == 0) {
            out_i[(size_t)b * KSEL + it] = c.w;
            chosen[it] = (int)c.w;
        }
        #pragma unroll
        for (int m = 0; m < 16; m++) {
            float ex = __fsub_rn(px[m], c.x), ey = __fsub_rn(py[m], c.y), ez = __fsub_rn(pz[m], c.z);
            float d2 = __fadd_rn(__fadd_rn(__fmul_rn(ex, ex), __fmul_rn(ey, ey)), __fmul_rn(ez, ez));
            mind[m] = fminf(mind[m], d2);
        }
    }
    __syncwarp();

    // MLP + softplus: lane l handles selection l
    int orig = chosen[l];
    const float* xr = x + ((size_t)b * NPTS + orig) * 32;
    float xv[32];
    #pragma unroll
    for (int i = 0; i < 32; i++) xv[i] = xr[i];

    float h1[16];
    #pragma unroll
    for (int o = 0; o < 16; o++) {
        float a = __ldg(&b1[o]);
        #pragma unroll
        for (int i = 0; i < 32; i++) a = fmaf(xv[i], __ldg(&W1[i * 16 + o]), a);
        h1[o] = fmaxf(a, 0.0f);
    }
    float h2[8];
    #pragma unroll
    for (int o = 0; o < 8; o++) {
        float a = __ldg(&b2[o]);
        #pragma unroll
        for (int i = 0; i < 16; i++) a = fmaf(h1[i], __ldg(&W2[i * 8 + o]), a);
        h2[o] = fmaxf(a, 0.0f);
    }
    float s = __ldg(&b3[0]);
    #pragma unroll
    for (int i = 0; i < 8; i++) s = fmaf(h2[i], __ldg(&W3[i]), s);
    float sp = fmaxf(s, 0.0f) + log1pf(expf(-fabsf(s)));
    out_w[(size_t)b * KSEL + l] = sp;
}

extern "C" void kernel_launch(void* const* d_in, const int* in_sizes, int n_in,
                              void* d_out, int out_size) {
    const float* x   = (const float*)d_in[0];
    const float* pos = (const float*)d_in[1];
    const float* W1  = (const float*)d_in[3];
    const float* b1  = (const float*)d_in[4];
    const float* W2  = (const float*)d_in[5];
    const float* b2  = (const float*)d_in[6];
    const float* W3  = (const float*)d_in[7];
    const float* b3  = (const float*)d_in[8];

    int n_points = in_sizes[0] / 32;      // B * 1024
    int B = n_points / NPTS;
    if (B > BMAX) B = BMAX;

    float* out_w = (float*)d_out;
    float* out_i = out_w + (size_t)B * KSEL;

    sort_kernel<<<B, T1>>>(pos);
    fps_mlp_kernel<<<B, 32>>>(x, W1, b1, W2, b2, W3, b3, out_w, out_i);
}

// round 4
// speedup vs baseline: 2.7491x; 1.0678x over previous
#include <cuda_runtime.h>
#include <cuda_bf16.h>
#include <math.h>

// Detector: per-submap (1024 pts) -> top-512 by xy-dist (rank-ordered) -> FPS 32 -> MLP gather.
// K1: bitonic sort, 256 thr x 4 elem (register exchanges for j<=64), writes ranked float4 scratch.
// K2: one warp per submap: register FPS (16 pts/lane, tree argmax + REDUX) + fused MLP (shared weights).

#define NPTS 1024
#define KPOS 512
#define KSEL 32
#define T1   256
#define BMAX 2048

// shared weight layout offsets (floats)
#define W1_OFF 0
#define B1_OFF 512
#define W2_OFF 528
#define B2_OFF 656
#define W3_OFF 664
#define B3_OFF 672
#define WTOT   673

typedef unsigned long long u64;
typedef unsigned int u32;

__device__ float4 g_selp[(size_t)BMAX * KPOS];   // 16.8 MB static scratch

__device__ __forceinline__ u64 shfl_xor_u64(u64 v, int m) {
    u32 lo = __shfl_xor_sync(0xffffffffu, (u32)v, m);
    u32 hi = __shfl_xor_sync(0xffffffffu, (u32)(v >> 32), m);
    return ((u64)hi << 32) | lo;
}
__device__ __forceinline__ u64 umin64(u64 a, u64 b) { return a < b ? a : b; }
__device__ __forceinline__ u64 umax64(u64 a, u64 b) { return a > b ? a : b; }

template<int JMAX>
__device__ __forceinline__ void shfl_steps(u64* e, int l, int w, unsigned k) {
    #pragma unroll
    for (int j = JMAX; j >= 1; j >>= 1) {
        #pragma unroll
        for (int m = 0; m < 4; m++) {
            int i = (w << 7) + (m << 5) + l;
            bool up = ((i & k) == 0);
            bool lower = ((l & j) == 0);
            u64 p = shfl_xor_u64(e[m], j);
            e[m] = (lower == up) ? umin64(e[m], p) : umax64(e[m], p);
        }
    }
}

__device__ __forceinline__ void intra_step(u64* e, int l, int w, unsigned k, int mbit) {
    #pragma unroll
    for (int m = 0; m < 4; m++) {
        int mp = m ^ (1 << mbit);
        if (mp > m) {
            int i = (w << 7) + (m << 5) + l;
            bool up = ((i & k) == 0);
            u64 lo = umin64(e[m], e[mp]), hi = umax64(e[m], e[mp]);
            e[m] = up ? lo : hi;
            e[mp] = up ? hi : lo;
        }
    }
}

__device__ __forceinline__ void shared_pass2(u64* skv, int t, int j, unsigned k) {
    #pragma unroll
    for (int s = 0; s < 2; s++) {
        int tt = t + s * T1;
        int i = ((tt & ~(j - 1)) << 1) | (tt & (j - 1));
        int p = i + j;
        bool up = ((i & k) == 0);
        u64 a = skv[i], b = skv[p];
        u64 lo = umin64(a, b), hi = umax64(a, b);
        skv[i] = up ? lo : hi;
        skv[p] = up ? hi : lo;
    }
}

__device__ __forceinline__ void store_regs(u64* skv, const u64* e, int l, int w) {
    #pragma unroll
    for (int m = 0; m < 4; m++) skv[(w << 7) + (m << 5) + l] = e[m];
}
__device__ __forceinline__ void load_regs(u64* skv, u64* e, int l, int w) {
    #pragma unroll
    for (int m = 0; m < 4; m++) e[m] = skv[(w << 7) + (m << 5) + l];
}

__global__ __launch_bounds__(T1) void sort_kernel(const float* __restrict__ pos)
{
    __shared__ u64 skv[NPTS];
    const int b = blockIdx.x;
    const int t = threadIdx.x;
    const int l = t & 31, w = t >> 5;
    const size_t base = (size_t)b * NPTS;

    u64 e[4];
    #pragma unroll
    for (int m = 0; m < 4; m++) {
        int i = (w << 7) + (m << 5) + l;
        float px = pos[(base + i) * 3 + 0];
        float py = pos[(base + i) * 3 + 1];
        float d = __fsqrt_rn(__fadd_rn(__fmul_rn(px, px), __fmul_rn(py, py)));
        e[m] = ((u64)__float_as_uint(d) << 32) | (u32)i;
    }

    // rounds k=2..128: registers only
    shfl_steps<1>(e, l, w, 2u);
    shfl_steps<2>(e, l, w, 4u);
    shfl_steps<4>(e, l, w, 8u);
    shfl_steps<8>(e, l, w, 16u);
    shfl_steps<16>(e, l, w, 32u);
    intra_step(e, l, w, 64u, 0);  shfl_steps<16>(e, l, w, 64u);
    intra_step(e, l, w, 128u, 1); intra_step(e, l, w, 128u, 0); shfl_steps<16>(e, l, w, 128u);

    // k=256
    store_regs(skv, e, l, w); __syncthreads();
    shared_pass2(skv, t, 128, 256u); __syncthreads();
    load_regs(skv, e, l, w);
    intra_step(e, l, w, 256u, 1); intra_step(e, l, w, 256u, 0); shfl_steps<16>(e, l, w, 256u);

    // k=512
    store_regs(skv, e, l, w); __syncthreads();
    shared_pass2(skv, t, 256, 512u); __syncthreads();
    shared_pass2(skv, t, 128, 512u); __syncthreads();
    load_regs(skv, e, l, w);
    intra_step(e, l, w, 512u, 1); intra_step(e, l, w, 512u, 0); shfl_steps<16>(e, l, w, 512u);

    // k=1024
    store_regs(skv, e, l, w); __syncthreads();
    shared_pass2(skv, t, 512, 1024u); __syncthreads();
    shared_pass2(skv, t, 256, 1024u); __syncthreads();
    shared_pass2(skv, t, 128, 1024u); __syncthreads();
    load_regs(skv, e, l, w);
    intra_step(e, l, w, 1024u, 1); intra_step(e, l, w, 1024u, 0); shfl_steps<16>(e, l, w, 1024u);

    // ranks 0..511 live in warps 0..3; write (x,y,z,origidx) in rank order
    if (w < 4) {
        #pragma unroll
        for (int m = 0; m < 4; m++) {
            int rank = (w << 7) + (m << 5) + l;
            int orig = (int)(u32)e[m];
            const float* pp = pos + (base + orig) * 3;
            g_selp[(size_t)b * KPOS + rank] = make_float4(pp[0], pp[1], pp[2], (float)orig);
        }
    }
}

__global__ __launch_bounds__(32) void fps_mlp_kernel(
    const float* __restrict__ x,
    const float* __restrict__ W1, const float* __restrict__ b1,
    const float* __restrict__ W2, const float* __restrict__ b2,
    const float* __restrict__ W3, const float* __restrict__ b3,
    float* __restrict__ out_w, float* __restrict__ out_i)
{
    __shared__ float4 selp[KPOS];
    __shared__ int chosen[KSEL];
    __shared__ float wsh[WTOT];

    const int b = blockIdx.x;
    const int l = threadIdx.x;
    const unsigned FULL = 0xffffffffu;

    // stage weights to shared (broadcast reads later)
    for (int i = l; i < WTOT; i += 32) {
        float v;
        if (i < B1_OFF)       v = W1[i];
        else if (i < W2_OFF)  v = b1[i - B1_OFF];
        else if (i < B2_OFF)  v = W2[i - W2_OFF];
        else if (i < W3_OFF)  v = b2[i - B2_OFF];
        else if (i < B3_OFF)  v = W3[i - W3_OFF];
        else                  v = b3[0];
        wsh[i] = v;
    }

    float px[16], py[16], pz[16];
    #pragma unroll
    for (int m = 0; m < 16; m++) {
        float4 f = g_selp[(size_t)b * KPOS + (m << 5) + l];
        selp[(m << 5) + l] = f;
        px[m] = f.x; py[m] = f.y; pz[m] = f.z;
    }
    __syncwarp();

    float4 p0 = selp[0];
    if (l == 0) {
        out_i[(size_t)b * KSEL + 0] = p0.w;
        chosen[0] = (int)p0.w;
    }

    float mind[16];
    #pragma unroll
    for (int m = 0; m < 16; m++) {
        float dx = __fsub_rn(px[m], p0.x), dy = __fsub_rn(py[m], p0.y), dz = __fsub_rn(pz[m], p0.z);
        mind[m] = __fadd_rn(__fadd_rn(__fmul_rn(dx, dx), __fmul_rn(dy, dy)), __fmul_rn(dz, dz));
    }

    for (int it = 1; it < KSEL; ++it) {
        // local argmax, depth-4 tree, key = (mindbits << 32) | (511 - rank)
        u64 kv[8];
        #pragma unroll
        for (int m = 0; m < 8; m++) {
            u64 a = ((u64)__float_as_uint(mind[2 * m])     << 32) | (u32)(511 - ((2 * m)     * 32 + l));
            u64 c = ((u64)__float_as_uint(mind[2 * m + 1]) << 32) | (u32)(511 - ((2 * m + 1) * 32 + l));
            kv[m] = umax64(a, c);
        }
        #pragma unroll
        for (int m = 0; m < 4; m++) kv[m] = umax64(kv[m], kv[m + 4]);
        kv[0] = umax64(kv[0], kv[2]);
        kv[1] = umax64(kv[1], kv[3]);
        u64 best = umax64(kv[0], kv[1]);

        // cross-lane: REDUX on float bits, then REDUX on masked rank key (min-rank tie-break)
        u32 hb = (u32)(best >> 32);
        u32 gmax = __reduce_max_sync(FULL, hb);
        u32 cand = (hb == gmax) ? (u32)best : 0u;
        u32 gl = __reduce_max_sync(FULL, cand);
        int sel = 511 - (int)gl;

        float4 c = selp[sel];        // broadcast
        if (l == 0) {
            out_i[(size_t)b * KSEL + it] = c.w;
            chosen[it] = (int)c.w;
        }
        #pragma unroll
        for (int m = 0; m < 16; m++) {
            float ex = __fsub_rn(px[m], c.x), ey = __fsub_rn(py[m], c.y), ez = __fsub_rn(pz[m], c.z);
            float d2 = __fadd_rn(__fadd_rn(__fmul_rn(ex, ex), __fmul_rn(ey, ey)), __fmul_rn(ez, ez));
            mind[m] = fminf(mind[m], d2);
        }
    }
    __syncwarp();

    // MLP + softplus: lane l handles selection l (weights from shared, broadcast)
    int orig = chosen[l];
    const float* xr = x + ((size_t)b * NPTS + orig) * 32;
    float xv[32];
    #pragma unroll
    for (int i = 0; i < 32; i++) xv[i] = xr[i];

    float h1[16];
    #pragma unroll
    for (int o = 0; o < 16; o++) {
        float a = wsh[B1_OFF + o];
        #pragma unroll
        for (int i = 0; i < 32; i++) a = fmaf(xv[i], wsh[W1_OFF + i * 16 + o], a);
        h1[o] = fmaxf(a, 0.0f);
    }
    float h2[8];
    #pragma unroll
    for (int o = 0; o < 8; o++) {
        float a = wsh[B2_OFF + o];
        #pragma unroll
        for (int i = 0; i < 16; i++) a = fmaf(h1[i], wsh[W2_OFF + i * 8 + o], a);
        h2[o] = fmaxf(a, 0.0f);
    }
    float s = wsh[B3_OFF];
    #pragma unroll
    for (int i = 0; i < 8; i++) s = fmaf(h2[i], wsh[W3_OFF + i], s);
    float sp = fmaxf(s, 0.0f) + log1pf(expf(-fabsf(s)));
    out_w[(size_t)b * KSEL + l] = sp;
}

extern "C" void kernel_launch(void* const* d_in, const int* in_sizes, int n_in,
                              void* d_out, int out_size) {
    const float* x   = (const float*)d_in[0];
    const float* pos = (const float*)d_in[1];
    const float* W1  = (const float*)d_in[3];
    const float* b1  = (const float*)d_in[4];
    const float* W2  = (const float*)d_in[5];
    const float* b2  = (const float*)d_in[6];
    const float* W3  = (const float*)d_in[7];
    const float* b3  = (const float*)d_in[8];

    int n_points = in_sizes[0] / 32;      // B * 1024
    int B = n_points / NPTS;
    if (B > BMAX) B = BMAX;

    float* out_w = (float*)d_out;
    float* out_i = out_w + (size_t)B * KSEL;

    sort_kernel<<<B, T1>>>(pos);
    fps_mlp_kernel<<<B, 32>>>(x, W1, b1, W2, b2, W3, b3, out_w, out_i);
}

// round 5
// speedup vs baseline: 4.5259x; 1.6463x over previous
#include <cuda_runtime.h>
#include <cuda_bf16.h>
#include <math.h>

// Detector: per-submap (1024 pts) -> top-512 by xy-dist -> FPS 32 -> MLP gather.
// K1: radix-select (shared histogram) + block-scan compaction -> 512 member points + start slot.
// K2: one warp per submap: register FPS (16 pts/lane, tree argmax + REDUX) + fused MLP.

#define NPTS 1024
#define KPOS 512
#define KSEL 32
#define T1   256
#define BMAX 2048

// shared weight layout offsets (floats)
#define W1_OFF 0
#define B1_OFF 512
#define W2_OFF 528
#define B2_OFF 656
#define W3_OFF 664
#define B3_OFF 672
#define WTOT   673

typedef unsigned long long u64;
typedef unsigned int u32;

__device__ float4 g_selp[(size_t)BMAX * KPOS];   // compacted (x,y,z,idx)
__device__ int    g_start[BMAX];                 // start slot (rank-0 element)

__device__ __forceinline__ u64 umax64(u64 a, u64 b) { return a > b ? a : b; }

// ---------------- K1: select top-512 + compact ----------------
__global__ __launch_bounds__(T1) void select_kernel(const float* __restrict__ pos)
{
    __shared__ u32 sdist[NPTS];
    __shared__ u32 hist[256];
    __shared__ u32 warpsum[8];
    __shared__ u32 bcast[2];
    __shared__ u32 s_dmin, s_imin;

    const int b = blockIdx.x, t = threadIdx.x;
    const int lane = t & 31, w = t >> 5;
    const size_t base = (size_t)b * NPTS;
    const unsigned FULL = 0xffffffffu;

    if (t == 0) { s_dmin = 0xffffffffu; s_imin = 0x7fffffffu; }
    __syncthreads();

    // distance bits for all 1024 pts (exact rn math, matches reference)
    u32 ldmin = 0xffffffffu;
    #pragma unroll
    for (int s = 0; s < 4; s++) {
        int i = s * T1 + t;
        float px = pos[(base + i) * 3 + 0];
        float py = pos[(base + i) * 3 + 1];
        u32 dbits = __float_as_uint(__fsqrt_rn(__fadd_rn(__fmul_rn(px, px), __fmul_rn(py, py))));
        sdist[i] = dbits;
        ldmin = min(ldmin, dbits);
    }
    atomicMin(&s_dmin, ldmin);
    __syncthreads();

    // rank-0 element = min distbits, tie min idx
    u32 dmin = s_dmin;
    #pragma unroll
    for (int s = 0; s < 4; s++) {
        int i = s * T1 + t;
        if (sdist[i] == dmin) atomicMin(&s_imin, (u32)i);
    }

    // radix select: find D = distbits of rank-511 element, r = rank within equal-D group
    u32 r = 511, prefix = 0;
    const u32 himask_tab[4] = {0u, 0xFF000000u, 0xFFFF0000u, 0xFFFFFF00u};
    #pragma unroll
    for (int pass = 0; pass < 4; pass++) {
        const int shift = 24 - 8 * pass;
        const u32 hm = himask_tab[pass];
        hist[t] = 0;                 // T1 == 256 bins
        __syncthreads();
        #pragma unroll
        for (int s = 0; s < 4; s++) {
            u32 v = sdist[s * T1 + t];
            if ((v & hm) == (prefix & hm)) atomicAdd(&hist[(v >> shift) & 255], 1);
        }
        __syncthreads();
        if (t < 32) {
            u32 c[8], ssum = 0;
            #pragma unroll
            for (int j = 0; j < 8; j++) { c[j] = hist[t * 8 + j]; ssum += c[j]; }
            u32 incl = ssum;
            #pragma unroll
            for (int o = 1; o < 32; o <<= 1) {
                u32 n = __shfl_up_sync(FULL, incl, o);
                if (lane >= o) incl += n;
            }
            u32 excl = incl - ssum;
            if (r >= excl && r < incl) {
                u32 run = excl;
                #pragma unroll
                for (int j = 0; j < 8; j++) {
                    if (r < run + c[j]) { bcast[0] = (u32)(t * 8 + j); bcast[1] = r - run; break; }
                    run += c[j];
                }
            }
        }
        __syncthreads();
        prefix |= bcast[0] << shift;
        r = bcast[1];
        __syncthreads();
    }
    const u32 D = prefix;

    // per-thread 4 consecutive elems for the scans
    const int i0 = t * 4;
    u32 v0 = sdist[i0], v1 = sdist[i0 + 1], v2 = sdist[i0 + 2], v3 = sdist[i0 + 3];

    // scan1: exclusive rank within the equal-D group (by idx)
    u32 f0 = (v0 == D), f1 = (v1 == D), f2 = (v2 == D), f3 = (v3 == D);
    u32 tsum = f0 + f1 + f2 + f3;
    u32 incl = tsum;
    #pragma unroll
    for (int o = 1; o < 32; o <<= 1) {
        u32 n = __shfl_up_sync(FULL, incl, o);
        if (lane >= o) incl += n;
    }
    if (lane == 31) warpsum[w] = incl;
    __syncthreads();
    if (t == 0) { u32 run = 0; for (int j = 0; j < 8; j++) { u32 tmp = warpsum[j]; warpsum[j] = run; run += tmp; } }
    __syncthreads();
    u32 gb = warpsum[w] + (incl - tsum);
    u32 g0 = gb, g1 = gb + f0, g2 = g1 + f1, g3 = g2 + f2;

    // membership: distbits < D, or == D with group-rank <= r
    u32 m0 = (v0 < D) || (f0 && g0 <= r);
    u32 m1 = (v1 < D) || (f1 && g1 <= r);
    u32 m2 = (v2 < D) || (f2 && g2 <= r);
    u32 m3 = (v3 < D) || (f3 && g3 <= r);
    __syncthreads();   // protect warpsum reuse

    // scan2: compact slots (idx order)
    u32 tsum2 = m0 + m1 + m2 + m3;
    u32 incl2 = tsum2;
    #pragma unroll
    for (int o = 1; o < 32; o <<= 1) {
        u32 n = __shfl_up_sync(FULL, incl2, o);
        if (lane >= o) incl2 += n;
    }
    if (lane == 31) warpsum[w] = incl2;
    __syncthreads();
    if (t == 0) { u32 run = 0; for (int j = 0; j < 8; j++) { u32 tmp = warpsum[j]; warpsum[j] = run; run += tmp; } }
    __syncthreads();
    u32 sb = warpsum[w] + (incl2 - tsum2);
    u32 s0 = sb, s1 = sb + m0, s2 = s1 + m1, s3 = s2 + m2;

    // write members (x,y,z,idx)
    float4* outp = g_selp + (size_t)b * KPOS;
    u32 mm[4] = {m0, m1, m2, m3};
    u32 ss[4] = {s0, s1, s2, s3};
    #pragma unroll
    for (int j = 0; j < 4; j++) {
        if (mm[j]) {
            int i = i0 + j;
            const float* pp = pos + (base + i) * 3;
            outp[ss[j]] = make_float4(pp[0], pp[1], pp[2], (float)i);
        }
    }

    // start slot = compact slot of the rank-0 element
    u32 imin = s_imin;
    if (imin >= (u32)i0 && imin < (u32)(i0 + 4)) {
        u32 sl = (imin == (u32)i0) ? s0 : (imin == (u32)i0 + 1) ? s1 : (imin == (u32)i0 + 2) ? s2 : s3;
        g_start[b] = (int)sl;
    }
}

// ---------------- K2: FPS + fused MLP ----------------
__global__ __launch_bounds__(32) void fps_mlp_kernel(
    const float* __restrict__ x,
    const float* __restrict__ W1, const float* __restrict__ b1,
    const float* __restrict__ W2, const float* __restrict__ b2,
    const float* __restrict__ W3, const float* __restrict__ b3,
    float* __restrict__ out_w, float* __restrict__ out_i)
{
    __shared__ float4 selp[KPOS];
    __shared__ int chosen[KSEL];
    __shared__ float wsh[WTOT];

    const int b = blockIdx.x;
    const int l = threadIdx.x;
    const unsigned FULL = 0xffffffffu;

    for (int i = l; i < WTOT; i += 32) {
        float v;
        if (i < B1_OFF)       v = W1[i];
        else if (i < W2_OFF)  v = b1[i - B1_OFF];
        else if (i < B2_OFF)  v = W2[i - W2_OFF];
        else if (i < W3_OFF)  v = b2[i - B2_OFF];
        else if (i < B3_OFF)  v = W3[i - W3_OFF];
        else                  v = b3[0];
        wsh[i] = v;
    }

    float px[16], py[16], pz[16];
    #pragma unroll
    for (int m = 0; m < 16; m++) {
        float4 f = g_selp[(size_t)b * KPOS + (m << 5) + l];
        selp[(m << 5) + l] = f;
        px[m] = f.x; py[m] = f.y; pz[m] = f.z;
    }
    __syncwarp();

    const int sslot = g_start[b];
    float4 p0 = selp[sslot];                 // broadcast
    if (l == 0) {
        out_i[(size_t)b * KSEL + 0] = p0.w;
        chosen[0] = (int)p0.w;
    }

    float mind[16];
    #pragma unroll
    for (int m = 0; m < 16; m++) {
        float dx = __fsub_rn(px[m], p0.x), dy = __fsub_rn(py[m], p0.y), dz = __fsub_rn(pz[m], p0.z);
        mind[m] = __fadd_rn(__fadd_rn(__fmul_rn(dx, dx), __fmul_rn(dy, dy)), __fmul_rn(dz, dz));
    }

    for (int it = 1; it < KSEL; ++it) {
        // local argmax tree, key = (mindbits << 32) | (511 - slot)
        u64 kv[8];
        #pragma unroll
        for (int m = 0; m < 8; m++) {
            u64 a = ((u64)__float_as_uint(mind[2 * m])     << 32) | (u32)(511 - ((2 * m)     * 32 + l));
            u64 c = ((u64)__float_as_uint(mind[2 * m + 1]) << 32) | (u32)(511 - ((2 * m + 1) * 32 + l));
            kv[m] = umax64(a, c);
        }
        #pragma unroll
        for (int m = 0; m < 4; m++) kv[m] = umax64(kv[m], kv[m + 4]);
        kv[0] = umax64(kv[0], kv[2]);
        kv[1] = umax64(kv[1], kv[3]);
        u64 best = umax64(kv[0], kv[1]);

        u32 hb = (u32)(best >> 32);
        u32 gmax = __reduce_max_sync(FULL, hb);
        u32 cand = (hb == gmax) ? (u32)best : 0u;
        u32 gl = __reduce_max_sync(FULL, cand);
        int sel = 511 - (int)gl;

        float4 c = selp[sel];                // broadcast
        if (l == 0) {
            out_i[(size_t)b * KSEL + it] = c.w;
            chosen[it] = (int)c.w;
        }
        #pragma unroll
        for (int m = 0; m < 16; m++) {
            float ex = __fsub_rn(px[m], c.x), ey = __fsub_rn(py[m], c.y), ez = __fsub_rn(pz[m], c.z);
            float d2 = __fadd_rn(__fadd_rn(__fmul_rn(ex, ex), __fmul_rn(ey, ey)), __fmul_rn(ez, ez));
            mind[m] = fminf(mind[m], d2);
        }
    }
    __syncwarp();

    // MLP + softplus: lane l handles selection l
    int orig = chosen[l];
    const float* xr = x + ((size_t)b * NPTS + orig) * 32;
    float xv[32];
    #pragma unroll
    for (int i = 0; i < 32; i++) xv[i] = xr[i];

    float h1[16];
    #pragma unroll
    for (int o = 0; o < 16; o++) {
        float a = wsh[B1_OFF + o];
        #pragma unroll
        for (int i = 0; i < 32; i++) a = fmaf(xv[i], wsh[W1_OFF + i * 16 + o], a);
        h1[o] = fmaxf(a, 0.0f);
    }
    float h2[8];
    #pragma unroll
    for (int o = 0; o < 8; o++) {
        float a = wsh[B2_OFF + o];
        #pragma unroll
        for (int i = 0; i < 16; i++) a = fmaf(h1[i], wsh[W2_OFF + i * 8 + o], a);
        h2[o] = fmaxf(a, 0.0f);
    }
    float s = wsh[B3_OFF];
    #pragma unroll
    for (int i = 0; i < 8; i++) s = fmaf(h2[i], wsh[W3_OFF + i], s);
    float sp = fmaxf(s, 0.0f) + log1pf(expf(-fabsf(s)));
    out_w[(size_t)b * KSEL + l] = sp;
}

extern "C" void kernel_launch(void* const* d_in, const int* in_sizes, int n_in,
                              void* d_out, int out_size) {
    const float* x   = (const float*)d_in[0];
    const float* pos = (const float*)d_in[1];
    const float* W1  = (const float*)d_in[3];
    const float* b1  = (const float*)d_in[4];
    const float* W2  = (const float*)d_in[5];
    const float* b2  = (const float*)d_in[6];
    const float* W3  = (const float*)d_in[7];
    const float* b3  = (const float*)d_in[8];

    int n_points = in_sizes[0] / 32;      // B * 1024
    int B = n_points / NPTS;
    if (B > BMAX) B = BMAX;

    float* out_w = (float*)d_out;
    float* out_i = out_w + (size_t)B * KSEL;

    select_kernel<<<B, T1>>>(pos);
    fps_mlp_kernel<<<B, 32>>>(x, W1, b1, W2, b2, W3, b3, out_w, out_i);
}

// round 6
// speedup vs baseline: 5.0948x; 1.1257x over previous
#include <cuda_runtime.h>
#include <cuda_bf16.h>
#include <math.h>

// Detector: per-submap (1024 pts) -> top-512 by xy-dist -> FPS 32 -> MLP gather.
// K1: radix-select (shared histogram) + block-scan compaction -> 512 member points + start slot.
// K2: 2 warps per submap: packed-f32x2 register FPS (8 pts/lane/warp) + fused MLP.

#define NPTS 1024
#define KPOS 512
#define KSEL 32
#define T1   256
#define BMAX 2048

#define W1_OFF 0
#define B1_OFF 512
#define W2_OFF 528
#define B2_OFF 656
#define W3_OFF 664
#define B3_OFF 672
#define WTOT   673

typedef unsigned long long u64;
typedef unsigned int u32;

__device__ float4 g_selp[(size_t)BMAX * KPOS];
__device__ int    g_start[BMAX];

__device__ __forceinline__ u64 umax64(u64 a, u64 b) { return a > b ? a : b; }

#define PACK_F32X2(out, lo, hi) \
    asm("mov.b64 %0, {%1, %2};" : "=l"(out) : "r"(lo), "r"(hi))
#define ADD_F32X2(out, a, b) \
    asm("add.rn.f32x2 %0, %1, %2;" : "=l"(out) : "l"(a), "l"(b))
#define MUL_F32X2(out, a, b) \
    asm("mul.rn.f32x2 %0, %1, %2;" : "=l"(out) : "l"(a), "l"(b))

// ---------------- K1: select top-512 + compact ----------------
__global__ __launch_bounds__(T1) void select_kernel(const float* __restrict__ pos)
{
    __shared__ u32 sdist[NPTS];
    __shared__ u32 hist[256];
    __shared__ u32 warpsum[8];
    __shared__ u32 bcast[2];
    __shared__ u32 s_dmin, s_imin;

    const int b = blockIdx.x, t = threadIdx.x;
    const int lane = t & 31, w = t >> 5;
    const size_t base = (size_t)b * NPTS;
    const unsigned FULL = 0xffffffffu;

    if (t == 0) { s_dmin = 0xffffffffu; s_imin = 0x7fffffffu; }
    __syncthreads();

    u32 ldmin = 0xffffffffu;
    #pragma unroll
    for (int s = 0; s < 4; s++) {
        int i = s * T1 + t;
        float px = pos[(base + i) * 3 + 0];
        float py = pos[(base + i) * 3 + 1];
        u32 dbits = __float_as_uint(__fsqrt_rn(__fadd_rn(__fmul_rn(px, px), __fmul_rn(py, py))));
        sdist[i] = dbits;
        ldmin = min(ldmin, dbits);
    }
    atomicMin(&s_dmin, ldmin);
    __syncthreads();

    u32 dmin = s_dmin;
    #pragma unroll
    for (int s = 0; s < 4; s++) {
        int i = s * T1 + t;
        if (sdist[i] == dmin) atomicMin(&s_imin, (u32)i);
    }

    u32 r = 511, prefix = 0;
    const u32 himask_tab[4] = {0u, 0xFF000000u, 0xFFFF0000u, 0xFFFFFF00u};
    #pragma unroll
    for (int pass = 0; pass < 4; pass++) {
        const int shift = 24 - 8 * pass;
        const u32 hm = himask_tab[pass];
        hist[t] = 0;
        __syncthreads();
        #pragma unroll
        for (int s = 0; s < 4; s++) {
            u32 v = sdist[s * T1 + t];
            if ((v & hm) == (prefix & hm)) atomicAdd(&hist[(v >> shift) & 255], 1);
        }
        __syncthreads();
        if (t < 32) {
            u32 c[8], ssum = 0;
            #pragma unroll
            for (int j = 0; j < 8; j++) { c[j] = hist[t * 8 + j]; ssum += c[j]; }
            u32 incl = ssum;
            #pragma unroll
            for (int o = 1; o < 32; o <<= 1) {
                u32 n = __shfl_up_sync(FULL, incl, o);
                if (lane >= o) incl += n;
            }
            u32 excl = incl - ssum;
            if (r >= excl && r < incl) {
                u32 run = excl;
                #pragma unroll
                for (int j = 0; j < 8; j++) {
                    if (r < run + c[j]) { bcast[0] = (u32)(t * 8 + j); bcast[1] = r - run; break; }
                    run += c[j];
                }
            }
        }
        __syncthreads();
        prefix |= bcast[0] << shift;
        r = bcast[1];
        __syncthreads();
    }
    const u32 D = prefix;

    const int i0 = t * 4;
    u32 v0 = sdist[i0], v1 = sdist[i0 + 1], v2 = sdist[i0 + 2], v3 = sdist[i0 + 3];

    u32 f0 = (v0 == D), f1 = (v1 == D), f2 = (v2 == D), f3 = (v3 == D);
    u32 tsum = f0 + f1 + f2 + f3;
    u32 incl = tsum;
    #pragma unroll
    for (int o = 1; o < 32; o <<= 1) {
        u32 n = __shfl_up_sync(FULL, incl, o);
        if (lane >= o) incl += n;
    }
    if (lane == 31) warpsum[w] = incl;
    __syncthreads();
    if (t == 0) { u32 run = 0; for (int j = 0; j < 8; j++) { u32 tmp = warpsum[j]; warpsum[j] = run; run += tmp; } }
    __syncthreads();
    u32 gb = warpsum[w] + (incl - tsum);
    u32 g0 = gb, g1 = gb + f0, g2 = g1 + f1, g3 = g2 + f2;

    u32 m0 = (v0 < D) || (f0 && g0 <= r);
    u32 m1 = (v1 < D) || (f1 && g1 <= r);
    u32 m2 = (v2 < D) || (f2 && g2 <= r);
    u32 m3 = (v3 < D) || (f3 && g3 <= r);
    __syncthreads();

    u32 tsum2 = m0 + m1 + m2 + m3;
    u32 incl2 = tsum2;
    #pragma unroll
    for (int o = 1; o < 32; o <<= 1) {
        u32 n = __shfl_up_sync(FULL, incl2, o);
        if (lane >= o) incl2 += n;
    }
    if (lane == 31) warpsum[w] = incl2;
    __syncthreads();
    if (t == 0) { u32 run = 0; for (int j = 0; j < 8; j++) { u32 tmp = warpsum[j]; warpsum[j] = run; run += tmp; } }
    __syncthreads();
    u32 sb = warpsum[w] + (incl2 - tsum2);
    u32 s0 = sb, s1 = sb + m0, s2 = s1 + m1, s3 = s2 + m2;

    float4* outp = g_selp + (size_t)b * KPOS;
    u32 mm[4] = {m0, m1, m2, m3};
    u32 ss[4] = {s0, s1, s2, s3};
    #pragma unroll
    for (int j = 0; j < 4; j++) {
        if (mm[j]) {
            int i = i0 + j;
            const float* pp = pos + (base + i) * 3;
            outp[ss[j]] = make_float4(pp[0], pp[1], pp[2], (float)i);
        }
    }

    u32 imin = s_imin;
    if (imin >= (u32)i0 && imin < (u32)(i0 + 4)) {
        u32 sl = (imin == (u32)i0) ? s0 : (imin == (u32)i0 + 1) ? s1 : (imin == (u32)i0 + 2) ? s2 : s3;
        g_start[b] = (int)sl;
    }
}

// ---------------- K2: FPS (2 warps, packed f32x2) + fused MLP ----------------
__global__ __launch_bounds__(64) void fps_mlp_kernel(
    const float* __restrict__ x,
    const float* __restrict__ W1, const float* __restrict__ b1,
    const float* __restrict__ W2, const float* __restrict__ b2,
    const float* __restrict__ W3, const float* __restrict__ b3,
    float* __restrict__ out_w, float* __restrict__ out_i)
{
    __shared__ float4 selp[KPOS];
    __shared__ int chosen[KSEL];
    __shared__ float wsh[WTOT];
    __shared__ u64 sred[2][2];

    const int b = blockIdx.x;
    const int t = threadIdx.x;
    const int l = t & 31, w = t >> 5;
    const unsigned FULL = 0xffffffffu;

    for (int i = t; i < WTOT; i += 64) {
        float v;
        if (i < B1_OFF)       v = W1[i];
        else if (i < W2_OFF)  v = b1[i - B1_OFF];
        else if (i < B2_OFF)  v = W2[i - W2_OFF];
        else if (i < W3_OFF)  v = b2[i - B2_OFF];
        else if (i < B3_OFF)  v = W3[i - W3_OFF];
        else                  v = b3[0];
        wsh[i] = v;
    }

    // warp w owns slots [w*256, w*256+256): 8 per lane, packed into 4 f32x2 pairs
    float fx[8], fy[8], fz[8];
    #pragma unroll
    for (int m = 0; m < 8; m++) {
        int slot = w * 256 + m * 32 + l;
        float4 f = g_selp[(size_t)b * KPOS + slot];
        selp[slot] = f;
        fx[m] = f.x; fy[m] = f.y; fz[m] = f.z;
    }
    u64 PX[4], PY[4], PZ[4];
    #pragma unroll
    for (int p = 0; p < 4; p++) {
        PACK_F32X2(PX[p], __float_as_uint(fx[2 * p]), __float_as_uint(fx[2 * p + 1]));
        PACK_F32X2(PY[p], __float_as_uint(fy[2 * p]), __float_as_uint(fy[2 * p + 1]));
        PACK_F32X2(PZ[p], __float_as_uint(fz[2 * p]), __float_as_uint(fz[2 * p + 1]));
    }
    __syncthreads();

    const int sslot = g_start[b];
    float4 p0 = selp[sslot];
    if (t == 0) {
        out_i[(size_t)b * KSEL + 0] = p0.w;
        chosen[0] = (int)p0.w;
    }

    // initial min_d: d2 = ((dx2+dy2)+dz2), dx = px + (-cx)  (IEEE-identical to px-cx)
    u64 NX, NY, NZ;
    {
        u32 nx = __float_as_uint(-p0.x), ny = __float_as_uint(-p0.y), nz = __float_as_uint(-p0.z);
        PACK_F32X2(NX, nx, nx); PACK_F32X2(NY, ny, ny); PACK_F32X2(NZ, nz, nz);
    }
    u64 md[4];
    #pragma unroll
    for (int p = 0; p < 4; p++) {
        u64 dx, dy, dz, xx, yy, zz, s1, s2;
        ADD_F32X2(dx, PX[p], NX); ADD_F32X2(dy, PY[p], NY); ADD_F32X2(dz, PZ[p], NZ);
        MUL_F32X2(xx, dx, dx); MUL_F32X2(yy, dy, dy); MUL_F32X2(zz, dz, dz);
        ADD_F32X2(s1, xx, yy); ADD_F32X2(s2, s1, zz);
        md[p] = s2;
    }

    const u32 rc = 511u - (u32)(w * 256) - (u32)l;   // 511 - slot(m=0)

    for (int it = 1; it < KSEL; ++it) {
        // warp-local max of distance bits (d2 >= 0 -> bit compare == float compare)
        u32 bl0 = (u32)md[0], bh0 = (u32)(md[0] >> 32);
        u32 bl1 = (u32)md[1], bh1 = (u32)(md[1] >> 32);
        u32 bl2 = (u32)md[2], bh2 = (u32)(md[2] >> 32);
        u32 bl3 = (u32)md[3], bh3 = (u32)(md[3] >> 32);
        u32 a0 = max(bl0, bh0), a1 = max(bl1, bh1), a2 = max(bl2, bh2), a3 = max(bl3, bh3);
        u32 lmax = max(max(a0, a1), max(a2, a3));
        u32 wmax = __reduce_max_sync(FULL, lmax);

        // min-slot among maxima: maximize (511 - slot)
        u32 c0 = (bl0 == wmax) ? (rc - 0)   : 0u;
        u32 c1 = (bh0 == wmax) ? (rc - 32)  : 0u;
        u32 c2 = (bl1 == wmax) ? (rc - 64)  : 0u;
        u32 c3 = (bh1 == wmax) ? (rc - 96)  : 0u;
        u32 c4 = (bl2 == wmax) ? (rc - 128) : 0u;
        u32 c5 = (bh2 == wmax) ? (rc - 160) : 0u;
        u32 c6 = (bl3 == wmax) ? (rc - 192) : 0u;
        u32 c7 = (bh3 == wmax) ? (rc - 224) : 0u;
        u32 cm = max(max(max(c0, c1), max(c2, c3)), max(max(c4, c5), max(c6, c7)));
        u32 wcand = __reduce_max_sync(FULL, cm);

        if (l == 0) sred[w][it & 1] = ((u64)wmax << 32) | wcand;
        __syncthreads();
        u64 best = umax64(sred[0][it & 1], sred[1][it & 1]);
        int sel = 511 - (int)(u32)best;

        float4 c = selp[sel];
        if (t == 0) {
            out_i[(size_t)b * KSEL + it] = c.w;
            chosen[it] = (int)c.w;
        }

        u32 nx = __float_as_uint(-c.x), ny = __float_as_uint(-c.y), nz = __float_as_uint(-c.z);
        PACK_F32X2(NX, nx, nx); PACK_F32X2(NY, ny, ny); PACK_F32X2(NZ, nz, nz);
        #pragma unroll
        for (int p = 0; p < 4; p++) {
            u64 dx, dy, dz, xx, yy, zz, s1, s2;
            ADD_F32X2(dx, PX[p], NX); ADD_F32X2(dy, PY[p], NY); ADD_F32X2(dz, PZ[p], NZ);
            MUL_F32X2(xx, dx, dx); MUL_F32X2(yy, dy, dy); MUL_F32X2(zz, dz, dz);
            ADD_F32X2(s1, xx, yy); ADD_F32X2(s2, s1, zz);
            // per-half integer min == float min for non-negative floats
            u32 mlo = min((u32)md[p], (u32)s2);
            u32 mhi = min((u32)(md[p] >> 32), (u32)(s2 >> 32));
            md[p] = ((u64)mhi << 32) | mlo;
        }
    }
    __syncthreads();

    // MLP + softplus on warp 0: lane l handles selection l
    if (t < KSEL) {
        int orig = chosen[t];
        const float* xr = x + ((size_t)b * NPTS + orig) * 32;
        float xv[32];
        #pragma unroll
        for (int i = 0; i < 32; i++) xv[i] = xr[i];

        float h1[16];
        #pragma unroll
        for (int o = 0; o < 16; o++) {
            float a = wsh[B1_OFF + o];
            #pragma unroll
            for (int i = 0; i < 32; i++) a = fmaf(xv[i], wsh[W1_OFF + i * 16 + o], a);
            h1[o] = fmaxf(a, 0.0f);
        }
        float h2[8];
        #pragma unroll
        for (int o = 0; o < 8; o++) {
            float a = wsh[B2_OFF + o];
            #pragma unroll
            for (int i = 0; i < 16; i++) a = fmaf(h1[i], wsh[W2_OFF + i * 8 + o], a);
            h2[o] = fmaxf(a, 0.0f);
        }
        float s = wsh[B3_OFF];
        #pragma unroll
        for (int i = 0; i < 8; i++) s = fmaf(h2[i], wsh[W3_OFF + i], s);
        float sp = fmaxf(s, 0.0f) + log1pf(expf(-fabsf(s)));
        out_w[(size_t)b * KSEL + t] = sp;
    }
}

extern "C" void kernel_launch(void* const* d_in, const int* in_sizes, int n_in,
                              void* d_out, int out_size) {
    const float* x   = (const float*)d_in[0];
    const float* pos = (const float*)d_in[1];
    const float* W1  = (const float*)d_in[3];
    const float* b1  = (const float*)d_in[4];
    const float* W2  = (const float*)d_in[5];
    const float* b2  = (const float*)d_in[6];
    const float* W3  = (const float*)d_in[7];
    const float* b3  = (const float*)d_in[8];

    int n_points = in_sizes[0] / 32;      // B * 1024
    int B = n_points / NPTS;
    if (B > BMAX) B = BMAX;

    float* out_w = (float*)d_out;
    float* out_i = out_w + (size_t)B * KSEL;

    select_kernel<<<B, T1>>>(pos);
    fps_mlp_kernel<<<B, 64>>>(x, W1, b1, W2, b2, W3, b3, out_w, out_i);
}